// round 8
// baseline (speedup 1.0000x reference)
#include <cuda_runtime.h>

// ---------------------------------------------------------------------------
// DSSIM loss: 1 - mean(SSIM(X,Y)), 11x11 Gaussian (sigma=1.5), depthwise C=3,
// zero SAME padding, HWC fp32 2160x3840x3.
//
// Two packed blur chains via (u,v)=(x+y,x-y); all SSIM terms recovered from
// blur(u),blur(v),blur(u^2),blur(v^2).
// Round-8 (= round-7 retry, infra failed): squares precomputed at store time
// into a second smem plane, so the horizontal tap is 2x LDS.64 + 2x fma2
// (no per-tap mul2). Prefetch distance 3 (register FIFO). No pad kernels.
// ---------------------------------------------------------------------------

using u64 = unsigned long long;

static constexpr int H    = 2160;
static constexpr int WC   = 3840 * 3;            // 11520 fused cols (w*C+c)
static constexpr int BX   = 256;
static constexpr int LW   = 288;                 // loaded cols [cb-16, cb+272)
static constexpr int CH   = 11;                  // rows per chunk (= ring depth)
static constexpr int OH   = 177;                 // output rows per block
static constexpr int GX   = WC / BX;             // 45
static constexpr int GY   = 13;                  // 13*177 = 2301 >= 2160
static constexpr int NBLK = GX * GY;             // 585 = 1.98 waves @ 296
static constexpr int QOFF = 2 * CH * LW;         // u64 offset of squares plane
static constexpr int SMEM_BYTES = 2 * QOFF * (int)sizeof(u64);   // 101376
static constexpr float SSIM_C1 = 1e-4f;
static constexpr float SSIM_C2 = 9e-4f;

__device__ float g_partial[NBLK];

__device__ __forceinline__ u64 pk2(float lo, float hi) {
    u64 r; asm("mov.b64 %0, {%1, %2};" : "=l"(r) : "f"(lo), "f"(hi)); return r;
}
__device__ __forceinline__ float2 up2(u64 a) {
    float2 f; asm("mov.b64 {%0, %1}, %2;" : "=f"(f.x), "=f"(f.y) : "l"(a)); return f;
}
__device__ __forceinline__ u64 fma2(u64 a, u64 b, u64 c) {
    u64 d; asm("fma.rn.f32x2 %0, %1, %2, %3;" : "=l"(d) : "l"(a), "l"(b), "l"(c)); return d;
}

extern __shared__ u64 dbuf[];   // [2][CH][LW] {u,v}  then  [2][CH][LW] {u^2,v^2}
#define BIDX(p, j, i) (((p) * CH + (j)) * LW + (i))

__global__ void __launch_bounds__(BX, 2)
ssim_main(const float* __restrict__ X, const float* __restrict__ Y) {
    __shared__ float red[BX];

    const float GWs[11] = {
        0.00102839f, 0.00759875f, 0.03600078f, 0.10936080f, 0.21300554f,
        0.26601173f,
        0.21300554f, 0.10936080f, 0.03600078f, 0.00759875f, 0.00102839f
    };
    u64 GW2[11];
#pragma unroll
    for (int k = 0; k < 11; ++k) GW2[k] = pk2(GWs[k], GWs[k]);

    const int  tid = threadIdx.x;
    const int  cb  = blockIdx.x * BX;
    const int  Rs  = blockIdx.y * OH;
    const bool xin = (blockIdx.x > 0) && (blockIdx.x < GX - 1);
    const bool ldr = tid < LW / 2;        // 144 loader threads, 2 cols each
    const int  c0  = 2 * tid;
    const int  g0  = cb - 16 + c0;

    // Chunks actually needed by this block (bottom band stops early).
    const int rows_here = (H - Rs < OH) ? (H - Rs) : OH;
    const int nch = (rows_here + 10 + CH - 1) / CH;

    auto ldrow = [&](int row) -> float4 {
        float x0 = 0.f, y0 = 0.f, x1 = 0.f, y1 = 0.f;
        if (row >= 0 && row < H) {
            const size_t b = (size_t)row * WC;
            if (xin) {
                const float2 xv = *(const float2*)(X + b + g0);
                const float2 yv = *(const float2*)(Y + b + g0);
                x0 = xv.x; x1 = xv.y; y0 = yv.x; y1 = yv.y;
            } else {
                if (g0 >= 0 && g0 < WC)         { x0 = X[b + g0];     y0 = Y[b + g0];     }
                if (g0 + 1 >= 0 && g0 + 1 < WC) { x1 = X[b + g0 + 1]; y1 = Y[b + g0 + 1]; }
            }
        }
        return make_float4(x0, y0, x1, y1);
    };
    // Store {u,v} and {u^2,v^2} for the 2 columns (two STS.128).
    auto sts = [&](int p, int j, float4 r) {
        const float u0 = r.x + r.y, v0 = r.x - r.y;
        const float u1 = r.z + r.w, v1 = r.z - r.w;
        const int bi = BIDX(p, j, c0);
        *(float4*)&dbuf[bi]        = make_float4(u0, v0, u1, v1);
        *(float4*)&dbuf[QOFF + bi] = make_float4(u0 * u0, v0 * v0, u1 * u1, v1 * v1);
    };

    // ---- prologue: fill buffer 0 with chunk 0 (independent rows, MLP=22) ----
    if (ldr) {
        float4 pr[CH];
#pragma unroll
        for (int j = 0; j < CH; ++j) pr[j] = ldrow(Rs - 5 + j);
#pragma unroll
        for (int j = 0; j < CH; ++j) sts(0, j, pr[j]);
    }
    __syncthreads();

    // Rings: packed (bu,bv) and (bu2,bv2) horizontal results.
    u64 ruv[11], rqq[11];
    float acc = 0.f;
    float4 st[3];                          // 3-deep prefetch FIFO

#pragma unroll 1
    for (int ch = 0; ch < nch; ++ch) {
        const int  pc  = ch & 1;
        const int  pn  = pc ^ 1;
        const int  rn0 = Rs - 5 + (ch + 1) * CH;
        const bool pf  = (ch + 1 < nch) && ldr;

#pragma unroll
        for (int j = 0; j < CH; ++j) {
            // -- pipelined prefetch, distance 3: STS(row j-3), LDG(row j) --
            if (pf) {
                if (j >= 3) sts(pn, j - 3, st[j % 3]);   // (j-3)%3 == j%3
                st[j % 3] = ldrow(rn0 + j);
            }

            // -- horizontal 11-tap conv: 2x LDS.64 + 2x fma2 per tap --
            u64 s1 = 0ull, s2 = 0ull;
            const int rb = BIDX(pc, j, tid + 1);
#pragma unroll
            for (int k = 0; k < 11; ++k) {
                const u64 uv = dbuf[rb + 3 * k];         // {u, v}
                const u64 qq = dbuf[QOFF + rb + 3 * k];  // {u^2, v^2}
                s1 = fma2(uv, GW2[k], s1);               // (Su,  Sv)
                s2 = fma2(qq, GW2[k], s2);               // (Su2, Sv2)
            }
            ruv[j] = s1; rqq[j] = s2;

            // -- vertical conv + SSIM once the ring is warm --
            const int t  = ch * CH + j;
            const int ro = Rs + t - 10;
            if (t >= 10 && ro < H) {
                u64 mu = 0ull, S = 0ull;
#pragma unroll
                for (int k = 0; k < 11; ++k) {
                    const int s = (j + 1 + k) % 11;      // compile-time slot
                    mu = fma2(ruv[s], GW2[k], mu);
                    S  = fma2(rqq[s], GW2[k], S);
                }
                const float2 m  = up2(mu);   // (bu,  bv)
                const float2 sv = up2(S);    // (bU2, bV2)
                const float p  = m.x * m.x;
                const float q  = m.y * m.y;
                const float A2 = p - q;           // 4*mux*muy
                const float B2 = p + q;           // 2*(mux^2+muy^2)
                const float D2 = sv.x - sv.y;     // 4*Sxy
                const float E2 = sv.x + sv.y;     // 2*(Sxx+Syy)
                const float num = (0.5f * A2 + SSIM_C1) *
                                  (0.5f * (D2 - A2) + SSIM_C2);
                const float den = (0.5f * B2 + SSIM_C1) *
                                  (0.5f * (E2 - B2) + SSIM_C2);
                acc += __fdividef(num, den);
            }
        }

        if (pf) {                           // flush FIFO tail: rows 8, 9, 10
            sts(pn,  8, st[2]);
            sts(pn,  9, st[0]);
            sts(pn, 10, st[1]);
        }
        __syncthreads();
    }

    // ---- deterministic block reduction ----
    red[tid] = acc;
    __syncthreads();
#pragma unroll
    for (int s = BX / 2; s > 0; s >>= 1) {
        if (tid < s) red[tid] += red[tid + s];
        __syncthreads();
    }
    if (tid == 0) g_partial[blockIdx.y * GX + blockIdx.x] = red[0];
}

__global__ void ssim_reduce(float* __restrict__ out) {
    __shared__ double red[256];
    double s = 0.0;
    for (int i = threadIdx.x; i < NBLK; i += 256) s += (double)g_partial[i];
    red[threadIdx.x] = s;
    __syncthreads();
    for (int k = 128; k > 0; k >>= 1) {
        if (threadIdx.x < k) red[threadIdx.x] += red[threadIdx.x + k];
        __syncthreads();
    }
    if (threadIdx.x == 0) {
        const double n = (double)H * (double)WC;
        out[0] = (float)(1.0 - red[0] / n);
    }
}

extern "C" void kernel_launch(void* const* d_in, const int* in_sizes, int n_in,
                              void* d_out, int out_size) {
    const float* X = (const float*)d_in[0];
    const float* Y = (const float*)d_in[1];
    cudaFuncSetAttribute(ssim_main, cudaFuncAttributeMaxDynamicSharedMemorySize,
                         SMEM_BYTES);
    dim3 grid(GX, GY);
    ssim_main<<<grid, BX, SMEM_BYTES>>>(X, Y);
    ssim_reduce<<<1, 256>>>((float*)d_out);
}

// round 10
// speedup vs baseline: 1.1295x; 1.1295x over previous
#include <cuda_runtime.h>

// ---------------------------------------------------------------------------
// DSSIM loss: 1 - mean(SSIM(X,Y)), 11x11 Gaussian (sigma=1.5), depthwise C=3,
// zero SAME padding, HWC fp32 2160x3840x3.
//
// Two packed blur chains via (u,v)=(x+y,x-y); all SSIM terms recovered from
// blur(u),blur(v),blur(u^2),blur(v^2). Smem holds packed {u,v} (8B/col);
// ld.shared.b64 feeds fma.rn.f32x2 directly.
// Round-10 (= round-9 retry, infra failed twice): 4-way buffer rotation,
// prefetch 2 chunks ahead, barrier every 2 chunks (9 vs 17), FIFO distance 4.
// ---------------------------------------------------------------------------

using u64 = unsigned long long;

static constexpr int H    = 2160;
static constexpr int WC   = 3840 * 3;            // 11520 fused cols (w*C+c)
static constexpr int BX   = 256;
static constexpr int LW   = 288;                 // loaded cols [cb-16, cb+272)
static constexpr int CH   = 11;                  // rows per chunk (= ring depth)
static constexpr int OH   = 177;                 // output rows per block
static constexpr int GX   = WC / BX;             // 45
static constexpr int GY   = 13;                  // 13*177 = 2301 >= 2160
static constexpr int NBLK = GX * GY;             // 585 = 1.98 waves @ 296
static constexpr int SMEM_BYTES = 4 * CH * LW * (int)sizeof(u64); // 101376
static constexpr float SSIM_C1 = 1e-4f;
static constexpr float SSIM_C2 = 9e-4f;

__device__ float g_partial[NBLK];

__device__ __forceinline__ u64 pk2(float lo, float hi) {
    u64 r; asm("mov.b64 %0, {%1, %2};" : "=l"(r) : "f"(lo), "f"(hi)); return r;
}
__device__ __forceinline__ float2 up2(u64 a) {
    float2 f; asm("mov.b64 {%0, %1}, %2;" : "=f"(f.x), "=f"(f.y) : "l"(a)); return f;
}
__device__ __forceinline__ u64 fma2(u64 a, u64 b, u64 c) {
    u64 d; asm("fma.rn.f32x2 %0, %1, %2, %3;" : "=l"(d) : "l"(a), "l"(b), "l"(c)); return d;
}
__device__ __forceinline__ u64 mul2(u64 a, u64 b) {
    u64 d; asm("mul.rn.f32x2 %0, %1, %2;" : "=l"(d) : "l"(a), "l"(b)); return d;
}

extern __shared__ u64 dbuf[];   // [4][CH][LW] of packed {u, v}
#define BIDX(p, j, i) (((p) * CH + (j)) * LW + (i))

__global__ void __launch_bounds__(BX, 2)
ssim_main(const float* __restrict__ X, const float* __restrict__ Y) {
    __shared__ float red[BX];

    const float GWs[11] = {
        0.00102839f, 0.00759875f, 0.03600078f, 0.10936080f, 0.21300554f,
        0.26601173f,
        0.21300554f, 0.10936080f, 0.03600078f, 0.00759875f, 0.00102839f
    };
    u64 GW2[11];
#pragma unroll
    for (int k = 0; k < 11; ++k) GW2[k] = pk2(GWs[k], GWs[k]);

    const int  tid = threadIdx.x;
    const int  cb  = blockIdx.x * BX;
    const int  Rs  = blockIdx.y * OH;
    const bool xin = (blockIdx.x > 0) && (blockIdx.x < GX - 1);
    const bool ldr = tid < LW / 2;        // 144 loader threads, 2 cols each
    const int  c0  = 2 * tid;
    const int  g0  = cb - 16 + c0;

    // Chunks actually needed by this block (bottom band stops early, >= 2).
    const int rows_here = (H - Rs < OH) ? (H - Rs) : OH;
    const int nch = (rows_here + 10 + CH - 1) / CH;

    auto ldrow = [&](int row) -> float4 {
        float x0 = 0.f, y0 = 0.f, x1 = 0.f, y1 = 0.f;
        if (row >= 0 && row < H) {
            const size_t b = (size_t)row * WC;
            if (xin) {
                const float2 xv = *(const float2*)(X + b + g0);
                const float2 yv = *(const float2*)(Y + b + g0);
                x0 = xv.x; x1 = xv.y; y0 = yv.x; y1 = yv.y;
            } else {
                if (g0 >= 0 && g0 < WC)         { x0 = X[b + g0];     y0 = Y[b + g0];     }
                if (g0 + 1 >= 0 && g0 + 1 < WC) { x1 = X[b + g0 + 1]; y1 = Y[b + g0 + 1]; }
            }
        }
        return make_float4(x0, y0, x1, y1);
    };
    // Store {u,v} for the 2 columns with one 16B write (c0 even).
    auto sts = [&](int p, int j, float4 r) {
        *(float4*)&dbuf[BIDX(p, j, c0)] =
            make_float4(r.x + r.y, r.x - r.y, r.z + r.w, r.z - r.w);
    };

    // ---- prologue: fill buffers 0 and 1 with chunks 0, 1 (MLP=22/pass) ----
    if (ldr) {
        float4 pr[CH];
#pragma unroll
        for (int j = 0; j < CH; ++j) pr[j] = ldrow(Rs - 5 + j);
#pragma unroll
        for (int j = 0; j < CH; ++j) sts(0, j, pr[j]);
#pragma unroll
        for (int j = 0; j < CH; ++j) pr[j] = ldrow(Rs - 5 + CH + j);
#pragma unroll
        for (int j = 0; j < CH; ++j) sts(1, j, pr[j]);
    }
    __syncthreads();

    // Rings: packed (bu,bv) and (bu2,bv2) horizontal results.
    u64 ruv[11], rqq[11];
    float acc = 0.f;
    float4 st[4];                          // 4-deep prefetch FIFO

#pragma unroll 1
    for (int ch = 0; ch < nch; ++ch) {
        const int  pc  = ch & 3;                       // compute buffer
        const int  pt  = (ch + 2) & 3;                 // prefetch target
        const int  rn0 = Rs - 5 + (ch + 2) * CH;       // 2 chunks ahead
        const bool pf  = (ch + 2 < nch) && ldr;

#pragma unroll
        for (int j = 0; j < CH; ++j) {
            // -- pipelined prefetch, distance 4: STS(row j-4), LDG(row j) --
            if (pf) {
                if (j >= 4) sts(pt, j - 4, st[j & 3]); // (j-4)&3 == j&3
                st[j & 3] = ldrow(rn0 + j);
            }

            // -- horizontal 11-tap conv, 2 packed chains --
            u64 s1 = 0ull, s2 = 0ull;
            const int rb = BIDX(pc, j, tid + 1);
#pragma unroll
            for (int k = 0; k < 11; ++k) {
                const u64 uv = dbuf[rb + 3 * k];        // LDS.64 -> reg pair
                s1 = fma2(uv, GW2[k], s1);              // (Su,  Sv)
                s2 = fma2(mul2(uv, uv), GW2[k], s2);    // (Su2, Sv2)
            }
            ruv[j] = s1; rqq[j] = s2;

            // -- vertical conv + SSIM once the ring is warm --
            const int t  = ch * CH + j;
            const int ro = Rs + t - 10;
            if (t >= 10 && ro < H) {
                u64 mu = 0ull, S = 0ull;
#pragma unroll
                for (int k = 0; k < 11; ++k) {
                    const int s = (j + 1 + k) % 11;     // compile-time slot
                    mu = fma2(ruv[s], GW2[k], mu);
                    S  = fma2(rqq[s], GW2[k], S);
                }
                const float2 m  = up2(mu);   // (bu,  bv)
                const float2 sv = up2(S);    // (bU2, bV2)
                const float p  = m.x * m.x;
                const float q  = m.y * m.y;
                const float A2 = p - q;           // 4*mux*muy
                const float B2 = p + q;           // 2*(mux^2+muy^2)
                const float D2 = sv.x - sv.y;     // 4*Sxy
                const float E2 = sv.x + sv.y;     // 2*(Sxx+Syy)
                const float num = (0.5f * A2 + SSIM_C1) *
                                  (0.5f * (D2 - A2) + SSIM_C2);
                const float den = (0.5f * B2 + SSIM_C1) *
                                  (0.5f * (E2 - B2) + SSIM_C2);
                acc += __fdividef(num, den);
            }
        }

        if (pf) {                           // flush FIFO tail: rows 7..10
            sts(pt,  7, st[3]);
            sts(pt,  8, st[0]);
            sts(pt,  9, st[1]);
            sts(pt, 10, st[2]);
        }
        if (ch & 1) __syncthreads();        // barrier every 2 chunks
    }

    // ---- deterministic block reduction ----
    red[tid] = acc;
    __syncthreads();
#pragma unroll
    for (int s = BX / 2; s > 0; s >>= 1) {
        if (tid < s) red[tid] += red[tid + s];
        __syncthreads();
    }
    if (tid == 0) g_partial[blockIdx.y * GX + blockIdx.x] = red[0];
}

__global__ void ssim_reduce(float* __restrict__ out) {
    __shared__ double red[256];
    double s = 0.0;
    for (int i = threadIdx.x; i < NBLK; i += 256) s += (double)g_partial[i];
    red[threadIdx.x] = s;
    __syncthreads();
    for (int k = 128; k > 0; k >>= 1) {
        if (threadIdx.x < k) red[threadIdx.x] += red[threadIdx.x + k];
        __syncthreads();
    }
    if (threadIdx.x == 0) {
        const double n = (double)H * (double)WC;
        out[0] = (float)(1.0 - red[0] / n);
    }
}

extern "C" void kernel_launch(void* const* d_in, const int* in_sizes, int n_in,
                              void* d_out, int out_size) {
    const float* X = (const float*)d_in[0];
    const float* Y = (const float*)d_in[1];
    cudaFuncSetAttribute(ssim_main, cudaFuncAttributeMaxDynamicSharedMemorySize,
                         SMEM_BYTES);
    dim3 grid(GX, GY);
    ssim_main<<<grid, BX, SMEM_BYTES>>>(X, Y);
    ssim_reduce<<<1, 256>>>((float*)d_out);
}

// round 11
// speedup vs baseline: 1.2111x; 1.0722x over previous
#include <cuda_runtime.h>

// ---------------------------------------------------------------------------
// DSSIM loss: 1 - mean(SSIM(X,Y)), 11x11 Gaussian (sigma=1.5), depthwise C=3,
// zero SAME padding, HWC fp32 2160x3840x3.
//
// Two packed blur chains via (u,v)=(x+y,x-y); all SSIM terms recovered from
// blur(u),blur(v),blur(u^2),blur(v^2). Smem holds packed {u,v} (8B/col);
// ld.shared.b64 feeds fma.rn.f32x2 directly. 4-way buffer rotation, prefetch
// 2 chunks ahead, barrier every 2 chunks.
// Round-11: prefetch flattened across ALL 256 threads (7 load-steps/thread
// instead of 11 on 144 loader threads) -> balanced warps, less barrier drift.
// ---------------------------------------------------------------------------

using u64 = unsigned long long;

static constexpr int H    = 2160;
static constexpr int WC   = 3840 * 3;            // 11520 fused cols (w*C+c)
static constexpr int BX   = 256;
static constexpr int LW   = 288;                 // loaded cols [cb-16, cb+272)
static constexpr int NPAIR= LW / 2;              // 144 column pairs per row
static constexpr int NIT  = NPAIR * 11;          // 1584 load items per chunk
static constexpr int CH   = 11;                  // rows per chunk (= ring depth)
static constexpr int OH   = 177;                 // output rows per block
static constexpr int GX   = WC / BX;             // 45
static constexpr int GY   = 13;                  // 13*177 = 2301 >= 2160
static constexpr int NBLK = GX * GY;             // 585 = 1.98 waves @ 296
static constexpr int SMEM_BYTES = 4 * CH * LW * (int)sizeof(u64); // 101376
static constexpr float SSIM_C1 = 1e-4f;
static constexpr float SSIM_C2 = 9e-4f;

__device__ float g_partial[NBLK];

__device__ __forceinline__ u64 pk2(float lo, float hi) {
    u64 r; asm("mov.b64 %0, {%1, %2};" : "=l"(r) : "f"(lo), "f"(hi)); return r;
}
__device__ __forceinline__ float2 up2(u64 a) {
    float2 f; asm("mov.b64 {%0, %1}, %2;" : "=f"(f.x), "=f"(f.y) : "l"(a)); return f;
}
__device__ __forceinline__ u64 fma2(u64 a, u64 b, u64 c) {
    u64 d; asm("fma.rn.f32x2 %0, %1, %2, %3;" : "=l"(d) : "l"(a), "l"(b), "l"(c)); return d;
}
__device__ __forceinline__ u64 mul2(u64 a, u64 b) {
    u64 d; asm("mul.rn.f32x2 %0, %1, %2;" : "=l"(d) : "l"(a), "l"(b)); return d;
}

extern __shared__ u64 dbuf[];   // [4][CH][LW] of packed {u, v}
#define BIDX(p, j, i) (((p) * CH + (j)) * LW + (i))

__global__ void __launch_bounds__(BX, 2)
ssim_main(const float* __restrict__ X, const float* __restrict__ Y) {
    __shared__ float red[BX];

    const float GWs[11] = {
        0.00102839f, 0.00759875f, 0.03600078f, 0.10936080f, 0.21300554f,
        0.26601173f,
        0.21300554f, 0.10936080f, 0.03600078f, 0.00759875f, 0.00102839f
    };
    u64 GW2[11];
#pragma unroll
    for (int k = 0; k < 11; ++k) GW2[k] = pk2(GWs[k], GWs[k]);

    const int  tid = threadIdx.x;
    const int  cb  = blockIdx.x * BX;
    const int  Rs  = blockIdx.y * OH;
    const bool xin = (blockIdx.x > 0) && (blockIdx.x < GX - 1);

    // Chunks actually needed by this block (bottom band stops early, >= 2).
    const int rows_here = (H - Rs < OH) ? (H - Rs) : OH;
    const int nch = (rows_here + 10 + CH - 1) / CH;

    // Load item "it" of a chunk whose first row is r0:
    //   row-in-chunk = it / NPAIR, column pair = it % NPAIR.
    auto ld_item = [&](int r0, int it) -> float4 {
        const int jr  = it / NPAIR;
        const int cp  = it - jr * NPAIR;
        const int row = r0 + jr;
        const int g0  = cb - 16 + 2 * cp;
        float x0 = 0.f, y0 = 0.f, x1 = 0.f, y1 = 0.f;
        if (row >= 0 && row < H) {
            const size_t b = (size_t)row * WC;
            if (xin) {
                const float2 xv = *(const float2*)(X + b + g0);
                const float2 yv = *(const float2*)(Y + b + g0);
                x0 = xv.x; x1 = xv.y; y0 = yv.x; y1 = yv.y;
            } else {
                if (g0 >= 0 && g0 < WC)         { x0 = X[b + g0];     y0 = Y[b + g0];     }
                if (g0 + 1 >= 0 && g0 + 1 < WC) { x1 = X[b + g0 + 1]; y1 = Y[b + g0 + 1]; }
            }
        }
        return make_float4(x0, y0, x1, y1);
    };
    // Store item "it" into buffer p as packed {u,v} (one STS.128).
    auto st_item = [&](int p, int it, float4 r) {
        const int jr = it / NPAIR;
        const int c0 = 2 * (it - jr * NPAIR);
        *(float4*)&dbuf[BIDX(p, jr, c0)] =
            make_float4(r.x + r.y, r.x - r.y, r.z + r.w, r.z - r.w);
    };

    // ---- prologue: fill buffers 0 and 1 with chunks 0, 1 (flat, all threads) ----
    for (int it = tid; it < NIT; it += BX) {
        st_item(0, it, ld_item(Rs - 5, it));
        st_item(1, it, ld_item(Rs - 5 + CH, it));
    }
    __syncthreads();

    // Rings: packed (bu,bv) and (bu2,bv2) horizontal results.
    u64 ruv[11], rqq[11];
    float acc = 0.f;
    float4 st[3];                          // 3-step prefetch FIFO

#pragma unroll 1
    for (int ch = 0; ch < nch; ++ch) {
        const int  pc  = ch & 3;                       // compute buffer
        const int  pt  = (ch + 2) & 3;                 // prefetch target
        const int  rp0 = Rs - 5 + (ch + 2) * CH;       // 2 chunks ahead
        const bool pf  = (ch + 2 < nch);

#pragma unroll
        for (int j = 0; j < CH; ++j) {
            // -- flat pipelined prefetch, distance 3 steps --
            //    load item (j*BX+tid) at steps 0..6, store it at steps 3..9
            if (pf) {
                if (j >= 3 && j <= 9) {
                    const int it = (j - 3) * BX + tid;
                    if ((j - 3) < 6 || it < NIT)       // j-3==6 is partial
                        st_item(pt, it, st[(j - 3) % 3]);
                }
                if (j <= 6) {
                    const int it = j * BX + tid;
                    if (j < 6 || it < NIT)             // j==6 is partial
                        st[j % 3] = ld_item(rp0, it);
                }
            }

            // -- horizontal 11-tap conv, 2 packed chains --
            u64 s1 = 0ull, s2 = 0ull;
            const int rb = BIDX(pc, j, tid + 1);
#pragma unroll
            for (int k = 0; k < 11; ++k) {
                const u64 uv = dbuf[rb + 3 * k];        // LDS.64 -> reg pair
                s1 = fma2(uv, GW2[k], s1);              // (Su,  Sv)
                s2 = fma2(mul2(uv, uv), GW2[k], s2);    // (Su2, Sv2)
            }
            ruv[j] = s1; rqq[j] = s2;

            // -- vertical conv + SSIM once the ring is warm --
            const int t  = ch * CH + j;
            const int ro = Rs + t - 10;
            if (t >= 10 && ro < H) {
                u64 mu = 0ull, S = 0ull;
#pragma unroll
                for (int k = 0; k < 11; ++k) {
                    const int s = (j + 1 + k) % 11;     // compile-time slot
                    mu = fma2(ruv[s], GW2[k], mu);
                    S  = fma2(rqq[s], GW2[k], S);
                }
                const float2 m  = up2(mu);   // (bu,  bv)
                const float2 sv = up2(S);    // (bU2, bV2)
                const float p  = m.x * m.x;
                const float q  = m.y * m.y;
                const float A2 = p - q;           // 4*mux*muy
                const float B2 = p + q;           // 2*(mux^2+muy^2)
                const float D2 = sv.x - sv.y;     // 4*Sxy
                const float E2 = sv.x + sv.y;     // 2*(Sxx+Syy)
                const float num = (0.5f * A2 + SSIM_C1) *
                                  (0.5f * (D2 - A2) + SSIM_C2);
                const float den = (0.5f * B2 + SSIM_C1) *
                                  (0.5f * (E2 - B2) + SSIM_C2);
                acc += __fdividef(num, den);
            }
        }

        if (ch & 1) __syncthreads();        // barrier every 2 chunks
    }

    // ---- deterministic block reduction ----
    red[tid] = acc;
    __syncthreads();
#pragma unroll
    for (int s = BX / 2; s > 0; s >>= 1) {
        if (tid < s) red[tid] += red[tid + s];
        __syncthreads();
    }
    if (tid == 0) g_partial[blockIdx.y * GX + blockIdx.x] = red[0];
}

__global__ void ssim_reduce(float* __restrict__ out) {
    __shared__ double red[256];
    double s = 0.0;
    for (int i = threadIdx.x; i < NBLK; i += 256) s += (double)g_partial[i];
    red[threadIdx.x] = s;
    __syncthreads();
    for (int k = 128; k > 0; k >>= 1) {
        if (threadIdx.x < k) red[threadIdx.x] += red[threadIdx.x + k];
        __syncthreads();
    }
    if (threadIdx.x == 0) {
        const double n = (double)H * (double)WC;
        out[0] = (float)(1.0 - red[0] / n);
    }
}

extern "C" void kernel_launch(void* const* d_in, const int* in_sizes, int n_in,
                              void* d_out, int out_size) {
    const float* X = (const float*)d_in[0];
    const float* Y = (const float*)d_in[1];
    cudaFuncSetAttribute(ssim_main, cudaFuncAttributeMaxDynamicSharedMemorySize,
                         SMEM_BYTES);
    dim3 grid(GX, GY);
    ssim_main<<<grid, BX, SMEM_BYTES>>>(X, Y);
    ssim_reduce<<<1, 256>>>((float*)d_out);
}